// round 4
// baseline (speedup 1.0000x reference)
#include <cuda_runtime.h>
#include <cstdint>
#include <math.h>

// B=64, S=512, Q=800, K=4, D=64  ->  GEMM: C[M=32768, N=64] = A[M,800] * Wq^T[800,64]
#define MDIM    32768
#define KDIM    800
#define NDIM    64
#define TM      128
#define TK      32
#define NITER   (KDIM / TK)   // 25
#define THREADS 512
#define STAGES  4

#define A_BYTES (TM * TK * 4)            // 16384
#define B_BYTES (NDIM * TK * 4)          //  8192
#define STAGE_BYTES (A_BYTES + B_BYTES)  // 24576
#define SMEM_TOTAL (STAGES * STAGE_BYTES)  // 98304

// ---------------------------------------------------------------------------
// helpers
// ---------------------------------------------------------------------------
__device__ __forceinline__ uint32_t f2tf(float x) {
    uint32_t r;
    asm("cvt.rna.tf32.f32 %0, %1;" : "=r"(r) : "f"(x));
    return r;
}
__device__ __forceinline__ uint32_t u2tf(uint32_t bits) {
    return f2tf(__uint_as_float(bits));
}

__device__ __forceinline__ void cp16(uint32_t dst, const void* src) {
    asm volatile("cp.async.cg.shared.global [%0], [%1], 16;" :: "r"(dst), "l"(src));
}

__device__ __forceinline__ void ldsm4(uint32_t& r0, uint32_t& r1, uint32_t& r2, uint32_t& r3,
                                      uint32_t addr) {
    asm volatile("ldmatrix.sync.aligned.m8n8.x4.shared.b16 {%0,%1,%2,%3}, [%4];"
                 : "=r"(r0), "=r"(r1), "=r"(r2), "=r"(r3) : "r"(addr));
}

__device__ __forceinline__ void mma_tf32(float* c,
                                         uint32_t a0, uint32_t a1, uint32_t a2, uint32_t a3,
                                         uint32_t b0, uint32_t b1) {
    asm volatile(
        "mma.sync.aligned.m16n8k8.row.col.f32.tf32.tf32.f32 "
        "{%0,%1,%2,%3}, {%4,%5,%6,%7}, {%8,%9}, {%0,%1,%2,%3};"
        : "+f"(c[0]), "+f"(c[1]), "+f"(c[2]), "+f"(c[3])
        : "r"(a0), "r"(a1), "r"(a2), "r"(a3), "r"(b0), "r"(b1));
}

// ---------------------------------------------------------------------------
// kernel: 16 warps, each owns a 16-row x 32-col C sub-tile
// ---------------------------------------------------------------------------
__global__ __launch_bounds__(THREADS, 2)
void ordinal_embed_kernel(const float* __restrict__ q,
                          const int*   __restrict__ rdat,
                          const float* __restrict__ Wq,   // [64, 800] row-major
                          const float* __restrict__ bq,   // [64]
                          const float* __restrict__ Wr,   // [4]
                          const float* __restrict__ br,   // [1]
                          float*       __restrict__ out)  // [32768, 64]
{
    // Dynamic smem: STAGES x { A[128x32] f32 swizzled, B[64x32] f32 swizzled }
    // element (row, k) at word offset row*TK + (k ^ ((row&7)*4))
    extern __shared__ uint8_t smem[];
    const uint32_t smemBase = (uint32_t)__cvta_generic_to_shared(smem);

    const int tid  = threadIdx.x;
    const int lane = tid & 31;
    const int w    = tid >> 5;         // warp 0..15
    const int mg   = w >> 1;           // m-group 0..7 -> rows [mg*16, mg*16+16)
    const int nh   = w & 1;            // n-half  0..1 -> cols [nh*32, nh*32+32)
    const int bm   = blockIdx.x;

    float acc[4][4];
    #pragma unroll
    for (int nt = 0; nt < 4; ++nt)
        #pragma unroll
        for (int i = 0; i < 4; ++i)
            acc[nt][i] = 0.0f;

    // ---- per-thread staging coordinates ------------------------------------
    // A tile: 1024 x 16B chunks -> 2 per thread; B tile: 512 -> 1 per thread
    const float* aRowBase = q + (size_t)bm * TM * KDIM;
    const float* aptr[2]; uint32_t asoff[2];
    #pragma unroll
    for (int i = 0; i < 2; ++i) {
        int ch = tid + THREADS * i;
        int m  = ch >> 3;
        int kq = (ch & 7) * 4;
        aptr[i]  = aRowBase + (size_t)m * KDIM + kq;
        asoff[i] = (uint32_t)(m * TK + (kq ^ ((m & 7) * 4))) * 4u;
    }
    const float* bptr;
    uint32_t bsoff;
    {
        int n  = tid >> 3;
        int kq = (tid & 7) * 4;
        bptr  = Wq + (size_t)n * KDIM + kq;
        bsoff = (uint32_t)(n * TK + (kq ^ ((n & 7) * 4))) * 4u + A_BYTES;
    }

    #define STAGE(IT)                                                       \
    do {                                                                    \
        const uint32_t _sb = smemBase + ((IT) % STAGES) * STAGE_BYTES;      \
        const int _k0 = (IT) * TK;                                          \
        cp16(_sb + asoff[0], aptr[0] + _k0);                                \
        cp16(_sb + asoff[1], aptr[1] + _k0);                                \
        cp16(_sb + bsoff,    bptr    + _k0);                                \
        asm volatile("cp.async.commit_group;");                             \
    } while (0)

    // ---- ldmatrix lane coordinates -----------------------------------------
    const int rA = mg * 16 + (lane & 15);
    const int cA = (lane >> 4) << 2;       // 0 or 4
    const int xA = (rA & 7) * 4;
    const int nBlow = (lane & 7) + ((lane >> 4) & 1) * 8;   // + p*16
    const int cB    = ((lane >> 3) & 1) * 4;                // 0 or 4

    // prologue: fill STAGES-1 stages
    STAGE(0); STAGE(1); STAGE(2);

    for (int it = 0; it < NITER; ++it) {
        asm volatile("cp.async.wait_group %0;" :: "n"(STAGES - 2));
        __syncthreads();

        if (it + STAGES - 1 < NITER) STAGE(it + STAGES - 1);

        const uint32_t sb = smemBase + (it % STAGES) * STAGE_BYTES;
        const uint32_t aB = sb;
        const uint32_t bB = sb + A_BYTES;

        #pragma unroll
        for (int k8 = 0; k8 < 4; ++k8) {
            uint32_t a0, a1, a2, a3;
            ldsm4(a0, a1, a2, a3,
                  aB + (uint32_t)(rA * TK + ((k8 * 8 + cA) ^ xA)) * 4u);
            a0 = u2tf(a0); a1 = u2tf(a1); a2 = u2tf(a2); a3 = u2tf(a3);

            uint32_t bf[2][4];
            #pragma unroll
            for (int p = 0; p < 2; ++p) {
                int n = nh * 32 + p * 16 + nBlow;
                ldsm4(bf[p][0], bf[p][1], bf[p][2], bf[p][3],
                      bB + (uint32_t)(n * TK + ((k8 * 8 + cB) ^ ((n & 7) * 4))) * 4u);
                #pragma unroll
                for (int j = 0; j < 4; ++j) bf[p][j] = u2tf(bf[p][j]);
            }

            #pragma unroll
            for (int nt = 0; nt < 4; ++nt)
                mma_tf32(acc[nt], a0, a1, a2, a3,
                         bf[nt >> 1][(nt & 1) * 2], bf[nt >> 1][(nt & 1) * 2 + 1]);
        }
        // No trailing sync needed: STAGE(it+STAGES-1) (issued after the top
        // barrier of iteration it) writes buffer (it-1)%STAGES, whose readers
        // all passed that same barrier.
    }

    // ---- epilogue: gate(r) * acc + bq ----
    const float wr0 = Wr[0], wr1 = Wr[1], wr2 = Wr[2], wr3 = Wr[3];
    const float brv = br[0];

    const int rbase = bm * TM + mg * 16 + (lane >> 2);
    #pragma unroll
    for (int h = 0; h < 2; ++h) {
        const int row = rbase + h * 8;
        const float rf = (float)rdat[row];
        float s = brv;
        s += fmaxf(1.0f - fabsf(0.0f - rf) * (1.0f / 3.0f), 0.0f) * wr0;
        s += fmaxf(1.0f - fabsf(1.0f - rf) * (1.0f / 3.0f), 0.0f) * wr1;
        s += fmaxf(1.0f - fabsf(2.0f - rf) * (1.0f / 3.0f), 0.0f) * wr2;
        s += fmaxf(1.0f - fabsf(3.0f - rf) * (1.0f / 3.0f), 0.0f) * wr3;
        const float gate = 1.0f / (1.0f + expf(-s));

        #pragma unroll
        for (int nt = 0; nt < 4; ++nt) {
            const int col = nh * 32 + nt * 8 + (lane & 3) * 2;
            float2 v;
            v.x = acc[nt][h * 2 + 0] * gate + bq[col];
            v.y = acc[nt][h * 2 + 1] * gate + bq[col + 1];
            *reinterpret_cast<float2*>(out + (size_t)row * NDIM + col) = v;
        }
    }
}

// ---------------------------------------------------------------------------
// launch
// ---------------------------------------------------------------------------
extern "C" void kernel_launch(void* const* d_in, const int* in_sizes, int n_in,
                              void* d_out, int out_size) {
    const float* q    = (const float*)d_in[0];   // [64,512,800] f32
    const int*   rdat = (const int*)  d_in[1];   // [64,512]     i32
    const float* Wq   = (const float*)d_in[2];   // [64,800]     f32
    const float* bq   = (const float*)d_in[3];   // [64]         f32
    const float* Wr   = (const float*)d_in[4];   // [1,4]        f32
    const float* br   = (const float*)d_in[5];   // [1]          f32
    float* out = (float*)d_out;                  // [64,512,64]  f32

    cudaFuncSetAttribute(ordinal_embed_kernel,
                         cudaFuncAttributeMaxDynamicSharedMemorySize, SMEM_TOTAL);
    ordinal_embed_kernel<<<MDIM / TM, THREADS, SMEM_TOTAL>>>(q, rdat, Wq, bq, Wr, br, out);
}

// round 5
// speedup vs baseline: 1.1294x; 1.1294x over previous
#include <cuda_runtime.h>
#include <cstdint>
#include <math.h>

// B=64, S=512, Q=800, K=4, D=64  ->  GEMM: C[M=32768, N=64] = A[M,800] * Wq^T[800,64]
#define MDIM    32768
#define KDIM    800
#define NDIM    64
#define TM      128
#define TKF     64            // floats per full k-stage (2 sub-tiles of 32)
#define NFULL   12            // 12 * 64 = 768
#define NIT     13            // + 1 tail stage of 32
#define THREADS 256

#define A_SUB   16384         // 128 rows * 32 floats * 4B
#define B_SUB   8192          // 64 rows * 32 floats * 4B
#define STAGE_BYTES (2*A_SUB + 2*B_SUB)   // 49152: [A0][A1][B0][B1]
#define SMEM_TOTAL  (2 * STAGE_BYTES)     // 98304

// ---------------------------------------------------------------------------
// helpers
// ---------------------------------------------------------------------------
__device__ __forceinline__ uint32_t f2tf(float x) {
    uint32_t r;
    asm("cvt.rna.tf32.f32 %0, %1;" : "=r"(r) : "f"(x));
    return r;
}
__device__ __forceinline__ uint32_t u2tf(uint32_t bits) {
    return f2tf(__uint_as_float(bits));
}

__device__ __forceinline__ void cp16(uint32_t dst, const void* src) {
    asm volatile("cp.async.cg.shared.global [%0], [%1], 16;" :: "r"(dst), "l"(src));
}

__device__ __forceinline__ void ldsm4(uint32_t& r0, uint32_t& r1, uint32_t& r2, uint32_t& r3,
                                      uint32_t addr) {
    asm volatile("ldmatrix.sync.aligned.m8n8.x4.shared.b16 {%0,%1,%2,%3}, [%4];"
                 : "=r"(r0), "=r"(r1), "=r"(r2), "=r"(r3) : "r"(addr));
}

__device__ __forceinline__ void mma_tf32(float* c,
                                         uint32_t a0, uint32_t a1, uint32_t a2, uint32_t a3,
                                         uint32_t b0, uint32_t b1) {
    asm volatile(
        "mma.sync.aligned.m16n8k8.row.col.f32.tf32.tf32.f32 "
        "{%0,%1,%2,%3}, {%4,%5,%6,%7}, {%8,%9}, {%0,%1,%2,%3};"
        : "+f"(c[0]), "+f"(c[1]), "+f"(c[2]), "+f"(c[3])
        : "r"(a0), "r"(a1), "r"(a2), "r"(a3), "r"(b0), "r"(b1));
}

// ---------------------------------------------------------------------------
// kernel: 8 warps, each owns 16 rows x 64 cols
// ---------------------------------------------------------------------------
__global__ __launch_bounds__(THREADS, 2)
void ordinal_embed_kernel(const float* __restrict__ q,
                          const int*   __restrict__ rdat,
                          const float* __restrict__ Wq,   // [64, 800] row-major
                          const float* __restrict__ bq,   // [64]
                          const float* __restrict__ Wr,   // [4]
                          const float* __restrict__ br,   // [1]
                          float*       __restrict__ out)  // [32768, 64]
{
    // Each 32-wide sub-tile uses word offset row*32 + (k ^ ((row&7)*4)).
    extern __shared__ uint8_t smem[];
    const uint32_t smemBase = (uint32_t)__cvta_generic_to_shared(smem);

    const int tid  = threadIdx.x;
    const int lane = tid & 31;
    const int w    = tid >> 5;         // warp 0..7 -> rows [w*16, w*16+16)
    const int bm   = blockIdx.x;

    float acc[8][4];
    #pragma unroll
    for (int nt = 0; nt < 8; ++nt)
        #pragma unroll
        for (int i = 0; i < 4; ++i)
            acc[nt][i] = 0.0f;

    // ---- full-stage staging coordinates ------------------------------------
    // chunk c = tid + 256*i.  A: i<8, m=c>>4 (=m0+16i), kq=(c&15)*4 (const).
    // B: i<4, n=c>>4 (=m0+16i).  Same kq, same swizzle XOR (n0&7==m0&7).
    const float* aRowBase = q + (size_t)bm * TM * KDIM;
    const int m0 = tid >> 4;
    const int kq = (tid & 15) * 4;                 // 0..60
    const float* aSrc0 = aRowBase + (size_t)m0 * KDIM + kq;
    const float* bSrc0 = Wq + (size_t)m0 * KDIM + kq;
    const uint32_t swz0 = (uint32_t)(m0 * 32 + ((kq & 31) ^ ((m0 & 7) * 4))) * 4u;
    const uint32_t aDst0 = (uint32_t)(kq >> 5) * A_SUB + swz0;
    const uint32_t bDst0 = 2u * A_SUB + (uint32_t)(kq >> 5) * B_SUB + swz0;

    #define STAGE_FULL(IT)                                                      \
    do {                                                                        \
        const uint32_t _sb = smemBase + ((IT) & 1) * STAGE_BYTES;               \
        const int _k0 = (IT) * TKF;                                             \
        _Pragma("unroll")                                                       \
        for (int i = 0; i < 8; ++i)                                             \
            cp16(_sb + aDst0 + (uint32_t)i * 2048u,                             \
                 aSrc0 + _k0 + (size_t)i * 16 * KDIM);                          \
        _Pragma("unroll")                                                       \
        for (int i = 0; i < 4; ++i)                                             \
            cp16(_sb + bDst0 + (uint32_t)i * 2048u,                             \
                 bSrc0 + _k0 + (size_t)i * 16 * KDIM);                          \
        asm volatile("cp.async.commit_group;");                                 \
    } while (0)

    // ---- tail-stage (last 32 floats, sub 0 only) ----------------------------
    #define STAGE_TAIL()                                                        \
    do {                                                                        \
        const uint32_t _sb = smemBase + (NFULL & 1) * STAGE_BYTES;              \
        const int _mt = tid >> 3;                                               \
        const int _kt = (tid & 7) * 4;                                          \
        const uint32_t _sw = (uint32_t)(_mt * 32 + (_kt ^ ((_mt & 7) * 4))) * 4u; \
        _Pragma("unroll")                                                       \
        for (int i = 0; i < 4; ++i)                                             \
            cp16(_sb + _sw + (uint32_t)i * 4096u,                               \
                 aRowBase + (size_t)(_mt + 32 * i) * KDIM + (NFULL * TKF) + _kt); \
        _Pragma("unroll")                                                       \
        for (int i = 0; i < 2; ++i)                                             \
            cp16(_sb + 2u * A_SUB + _sw + (uint32_t)i * 4096u,                  \
                 Wq + (size_t)(_mt + 32 * i) * KDIM + (NFULL * TKF) + _kt);     \
        asm volatile("cp.async.commit_group;");                                 \
    } while (0)

    // ---- ldmatrix lane coordinates -----------------------------------------
    const int rA = w * 16 + (lane & 15);
    const int cA = (lane >> 4) << 2;       // 0 or 4
    const int xA = (rA & 7) * 4;
    const int nBlow = (lane & 7) + ((lane >> 4) & 1) * 8;   // + p*16
    const int cB    = ((lane >> 3) & 1) * 4;                // 0 or 4

    #define COMPUTE_SUB(AB, BB)                                                 \
    do {                                                                        \
        _Pragma("unroll")                                                       \
        for (int k8 = 0; k8 < 4; ++k8) {                                        \
            uint32_t a0, a1, a2, a3;                                            \
            ldsm4(a0, a1, a2, a3,                                               \
                  (AB) + (uint32_t)(rA * 32 + ((k8 * 8 + cA) ^ xA)) * 4u);      \
            a0 = u2tf(a0); a1 = u2tf(a1); a2 = u2tf(a2); a3 = u2tf(a3);         \
            uint32_t bf[4][4];                                                  \
            _Pragma("unroll")                                                   \
            for (int p = 0; p < 4; ++p) {                                       \
                int n = p * 16 + nBlow;                                         \
                ldsm4(bf[p][0], bf[p][1], bf[p][2], bf[p][3],                   \
                      (BB) + (uint32_t)(n * 32 + ((k8 * 8 + cB) ^ ((n & 7) * 4))) * 4u); \
                _Pragma("unroll")                                               \
                for (int j = 0; j < 4; ++j) bf[p][j] = u2tf(bf[p][j]);          \
            }                                                                   \
            _Pragma("unroll")                                                   \
            for (int nt = 0; nt < 8; ++nt)                                      \
                mma_tf32(acc[nt], a0, a1, a2, a3,                               \
                         bf[nt >> 1][(nt & 1) * 2], bf[nt >> 1][(nt & 1) * 2 + 1]); \
        }                                                                       \
    } while (0)

    // ---- pipeline: 2 stages, distance-1 prefetch ---------------------------
    STAGE_FULL(0);

    for (int it = 0; it < NIT; ++it) {
        if (it + 1 < NFULL)       STAGE_FULL(it + 1);
        else if (it + 1 == NFULL) STAGE_TAIL();

        if (it + 1 < NIT) asm volatile("cp.async.wait_group 1;");
        else              asm volatile("cp.async.wait_group 0;");
        __syncthreads();

        const uint32_t sb = smemBase + (uint32_t)(it & 1) * STAGE_BYTES;
        if (it < NFULL) {
            COMPUTE_SUB(sb,         sb + 2u * A_SUB);
            COMPUTE_SUB(sb + A_SUB, sb + 2u * A_SUB + B_SUB);
        } else {
            COMPUTE_SUB(sb,         sb + 2u * A_SUB);
        }
        __syncthreads();   // protect buffer before next stage overwrites it
    }

    // ---- epilogue: gate(r) * acc + bq ----
    const float wr0 = Wr[0], wr1 = Wr[1], wr2 = Wr[2], wr3 = Wr[3];
    const float brv = br[0];

    const int rbase = bm * TM + w * 16 + (lane >> 2);
    #pragma unroll
    for (int h = 0; h < 2; ++h) {
        const int row = rbase + h * 8;
        const float rf = (float)rdat[row];
        float s = brv;
        s += fmaxf(1.0f - fabsf(0.0f - rf) * (1.0f / 3.0f), 0.0f) * wr0;
        s += fmaxf(1.0f - fabsf(1.0f - rf) * (1.0f / 3.0f), 0.0f) * wr1;
        s += fmaxf(1.0f - fabsf(2.0f - rf) * (1.0f / 3.0f), 0.0f) * wr2;
        s += fmaxf(1.0f - fabsf(3.0f - rf) * (1.0f / 3.0f), 0.0f) * wr3;
        const float gate = 1.0f / (1.0f + expf(-s));

        #pragma unroll
        for (int nt = 0; nt < 8; ++nt) {
            const int col = nt * 8 + (lane & 3) * 2;
            float2 v;
            v.x = acc[nt][h * 2 + 0] * gate + bq[col];
            v.y = acc[nt][h * 2 + 1] * gate + bq[col + 1];
            *reinterpret_cast<float2*>(out + (size_t)row * NDIM + col) = v;
        }
    }
}

// ---------------------------------------------------------------------------
// launch
// ---------------------------------------------------------------------------
extern "C" void kernel_launch(void* const* d_in, const int* in_sizes, int n_in,
                              void* d_out, int out_size) {
    const float* q    = (const float*)d_in[0];   // [64,512,800] f32
    const int*   rdat = (const int*)  d_in[1];   // [64,512]     i32
    const float* Wq   = (const float*)d_in[2];   // [64,800]     f32
    const float* bq   = (const float*)d_in[3];   // [64]         f32
    const float* Wr   = (const float*)d_in[4];   // [1,4]        f32
    const float* br   = (const float*)d_in[5];   // [1]          f32
    float* out = (float*)d_out;                  // [64,512,64]  f32

    cudaFuncSetAttribute(ordinal_embed_kernel,
                         cudaFuncAttributeMaxDynamicSharedMemorySize, SMEM_TOTAL);
    ordinal_embed_kernel<<<MDIM / TM, THREADS, SMEM_TOTAL>>>(q, rdat, Wq, bq, Wr, br, out);
}

// round 9
// speedup vs baseline: 1.2045x; 1.0665x over previous
#include <cuda_runtime.h>
#include <cstdint>
#include <math.h>

// B=64, S=512, Q=800, K=4, D=64  ->  GEMM: C[M=32768, N=64] = A[M,800] * Wq^T[800,64]
#define MDIM    32768
#define KDIM    800
#define NDIM    64
#define TM      128
#define TKF     64            // floats per full k-stage (2 sub-tiles of 32)
#define NFULL   12            // 12 * 64 = 768
#define NIT     13            // + 1 tail stage of 32
#define NSUB    25            // total 32-wide sub-stages
#define THREADS 256

#define A_SUB   16384         // 128 rows * 32 floats * 4B
#define B_SUB   8192          // 64 rows * 32 floats * 4B
#define STAGE_BYTES (2*A_SUB + 2*B_SUB)   // 49152: [A0][A1][B0][B1]
#define SMEM_TOTAL  (2 * STAGE_BYTES)     // 98304

// Pre-converted tf32 B, stored per 32-k sub-stage in the exact swizzled smem
// image: word (n, kk) of sub-stage s at  s*2048 + n*32 + (kk ^ ((n&7)*4))
__device__ uint32_t g_Bt[NSUB * NDIM * 32];   // 204.8 KB

// ---------------------------------------------------------------------------
// helpers
// ---------------------------------------------------------------------------
__device__ __forceinline__ uint32_t f2tf(float x) {
    uint32_t r;
    asm("cvt.rna.tf32.f32 %0, %1;" : "=r"(r) : "f"(x));
    return r;
}
__device__ __forceinline__ uint32_t u2tf(uint32_t bits) {
    return f2tf(__uint_as_float(bits));
}

__device__ __forceinline__ void cp16(uint32_t dst, const void* src) {
    asm volatile("cp.async.cg.shared.global [%0], [%1], 16;" :: "r"(dst), "l"(src));
}

__device__ __forceinline__ void ldsm4(uint32_t& r0, uint32_t& r1, uint32_t& r2, uint32_t& r3,
                                      uint32_t addr) {
    asm volatile("ldmatrix.sync.aligned.m8n8.x4.shared.b16 {%0,%1,%2,%3}, [%4];"
                 : "=r"(r0), "=r"(r1), "=r"(r2), "=r"(r3) : "r"(addr));
}

__device__ __forceinline__ void mma_tf32(float* c,
                                         uint32_t a0, uint32_t a1, uint32_t a2, uint32_t a3,
                                         uint32_t b0, uint32_t b1) {
    asm volatile(
        "mma.sync.aligned.m16n8k8.row.col.f32.tf32.tf32.f32 "
        "{%0,%1,%2,%3}, {%4,%5,%6,%7}, {%8,%9}, {%0,%1,%2,%3};"
        : "+f"(c[0]), "+f"(c[1]), "+f"(c[2]), "+f"(c[3])
        : "r"(a0), "r"(a1), "r"(a2), "r"(a3), "r"(b0), "r"(b1));
}

// ---------------------------------------------------------------------------
// pre-kernel: Wq -> tf32, swizzled smem image (per 32-k sub-stage)
// ---------------------------------------------------------------------------
__global__ void convert_B_kernel(const float* __restrict__ Wq) {
    int i = blockIdx.x * 256 + threadIdx.x;
    if (i < NSUB * 2048) {
        int s  = i >> 11;                          // sub-stage
        int wd = i & 2047;
        int n  = wd >> 5;                          // row 0..63
        int kk = (wd & 31) ^ ((n & 7) * 4);        // un-swizzle -> source k
        g_Bt[i] = f2tf(Wq[n * KDIM + s * 32 + kk]);
    }
}

// ---------------------------------------------------------------------------
// kernel: 8 warps, each owns 16 rows x 64 cols (identical to R5 except B path)
// ---------------------------------------------------------------------------
__global__ __launch_bounds__(THREADS, 2)
void ordinal_embed_kernel(const float* __restrict__ q,
                          const int*   __restrict__ rdat,
                          const float* __restrict__ bq,   // [64]
                          const float* __restrict__ Wr,   // [4]
                          const float* __restrict__ br,   // [1]
                          float*       __restrict__ out)  // [32768, 64]
{
    extern __shared__ uint8_t smem[];
    const uint32_t smemBase = (uint32_t)__cvta_generic_to_shared(smem);

    const int tid  = threadIdx.x;
    const int lane = tid & 31;
    const int w    = tid >> 5;         // warp 0..7 -> rows [w*16, w*16+16)
    const int bm   = blockIdx.x;

    float acc[8][4];
    #pragma unroll
    for (int nt = 0; nt < 8; ++nt)
        #pragma unroll
        for (int i = 0; i < 4; ++i)
            acc[nt][i] = 0.0f;

    // ---- A staging coordinates (identical to R5) ---------------------------
    const float* aRowBase = q + (size_t)bm * TM * KDIM;
    const int m0 = tid >> 4;
    const int kq = (tid & 15) * 4;                 // 0..60
    const float* aSrc0 = aRowBase + (size_t)m0 * KDIM + kq;
    const uint32_t swz0 = (uint32_t)(m0 * 32 + ((kq & 31) ^ ((m0 & 7) * 4))) * 4u;
    const uint32_t aDst0 = (uint32_t)(kq >> 5) * A_SUB + swz0;

    // ---- full-stage: A swizzled loads + B contiguous image copy ------------
    #define STAGE_FULL(IT)                                                      \
    do {                                                                        \
        const uint32_t _sb = smemBase + ((IT) & 1) * STAGE_BYTES;               \
        const int _k0 = (IT) * TKF;                                             \
        _Pragma("unroll")                                                       \
        for (int i = 0; i < 8; ++i)                                             \
            cp16(_sb + aDst0 + (uint32_t)i * 2048u,                             \
                 aSrc0 + _k0 + (size_t)i * 16 * KDIM);                          \
        _Pragma("unroll")                                                       \
        for (int i = 0; i < 4; ++i)                                             \
            cp16(_sb + 2u * A_SUB + (uint32_t)(tid + THREADS * i) * 16u,        \
                 g_Bt + (2 * (IT)) * 2048 + (tid + THREADS * i) * 4);           \
        asm volatile("cp.async.commit_group;");                                 \
    } while (0)

    // ---- tail-stage (last 32 floats, sub 0 only) ---------------------------
    #define STAGE_TAIL()                                                        \
    do {                                                                        \
        const uint32_t _sb = smemBase + (NFULL & 1) * STAGE_BYTES;              \
        const int _mt = tid >> 3;                                               \
        const int _kt = (tid & 7) * 4;                                          \
        const uint32_t _sw = (uint32_t)(_mt * 32 + (_kt ^ ((_mt & 7) * 4))) * 4u; \
        _Pragma("unroll")                                                       \
        for (int i = 0; i < 4; ++i)                                             \
            cp16(_sb + _sw + (uint32_t)i * 4096u,                               \
                 aRowBase + (size_t)(_mt + 32 * i) * KDIM + (NFULL * TKF) + _kt); \
        _Pragma("unroll")                                                       \
        for (int i = 0; i < 2; ++i)                                             \
            cp16(_sb + 2u * A_SUB + (uint32_t)(tid + THREADS * i) * 16u,        \
                 g_Bt + 24 * 2048 + (tid + THREADS * i) * 4);                   \
        asm volatile("cp.async.commit_group;");                                 \
    } while (0)

    // ---- ldmatrix lane coordinates (identical to R5) -----------------------
    const int rA = w * 16 + (lane & 15);
    const int cA = (lane >> 4) << 2;       // 0 or 4
    const int xA = (rA & 7) * 4;
    const int nBlow = (lane & 7) + ((lane >> 4) & 1) * 8;   // + p*16
    const int cB    = ((lane >> 3) & 1) * 4;                // 0 or 4

    #define COMPUTE_SUB(AB, BB)                                                 \
    do {                                                                        \
        _Pragma("unroll")                                                       \
        for (int k8 = 0; k8 < 4; ++k8) {                                        \
            uint32_t a0, a1, a2, a3;                                            \
            ldsm4(a0, a1, a2, a3,                                               \
                  (AB) + (uint32_t)(rA * 32 + ((k8 * 8 + cA) ^ xA)) * 4u);      \
            a0 = u2tf(a0); a1 = u2tf(a1); a2 = u2tf(a2); a3 = u2tf(a3);         \
            uint32_t bf[4][4];                                                  \
            _Pragma("unroll")                                                   \
            for (int p = 0; p < 4; ++p) {                                       \
                int n = p * 16 + nBlow;                                         \
                ldsm4(bf[p][0], bf[p][1], bf[p][2], bf[p][3],                   \
                      (BB) + (uint32_t)(n * 32 + ((k8 * 8 + cB) ^ ((n & 7) * 4))) * 4u); \
            }                                                                   \
            _Pragma("unroll")                                                   \
            for (int nt = 0; nt < 8; ++nt)                                      \
                mma_tf32(acc[nt], a0, a1, a2, a3,                               \
                         bf[nt >> 1][(nt & 1) * 2], bf[nt >> 1][(nt & 1) * 2 + 1]); \
        }                                                                       \
    } while (0)

    // ---- pipeline: 2 stages, distance-1 prefetch (identical to R5) ---------
    STAGE_FULL(0);

    for (int it = 0; it < NIT; ++it) {
        if (it + 1 < NFULL)       STAGE_FULL(it + 1);
        else if (it + 1 == NFULL) STAGE_TAIL();

        if (it + 1 < NIT) asm volatile("cp.async.wait_group 1;");
        else              asm volatile("cp.async.wait_group 0;");
        __syncthreads();

        const uint32_t sb = smemBase + (uint32_t)(it & 1) * STAGE_BYTES;
        if (it < NFULL) {
            COMPUTE_SUB(sb,         sb + 2u * A_SUB);
            COMPUTE_SUB(sb + A_SUB, sb + 2u * A_SUB + B_SUB);
        } else {
            COMPUTE_SUB(sb,         sb + 2u * A_SUB);
        }
        __syncthreads();   // protect buffer before next stage overwrites it
    }

    // ---- epilogue: gate(r) * acc + bq (identical to R5) --------------------
    const float wr0 = Wr[0], wr1 = Wr[1], wr2 = Wr[2], wr3 = Wr[3];
    const float brv = br[0];

    const int rbase = bm * TM + w * 16 + (lane >> 2);
    #pragma unroll
    for (int h = 0; h < 2; ++h) {
        const int row = rbase + h * 8;
        const float rf = (float)rdat[row];
        float s = brv;
        s += fmaxf(1.0f - fabsf(0.0f - rf) * (1.0f / 3.0f), 0.0f) * wr0;
        s += fmaxf(1.0f - fabsf(1.0f - rf) * (1.0f / 3.0f), 0.0f) * wr1;
        s += fmaxf(1.0f - fabsf(2.0f - rf) * (1.0f / 3.0f), 0.0f) * wr2;
        s += fmaxf(1.0f - fabsf(3.0f - rf) * (1.0f / 3.0f), 0.0f) * wr3;
        const float gate = 1.0f / (1.0f + expf(-s));

        #pragma unroll
        for (int nt = 0; nt < 8; ++nt) {
            const int col = nt * 8 + (lane & 3) * 2;
            float2 v;
            v.x = acc[nt][h * 2 + 0] * gate + bq[col];
            v.y = acc[nt][h * 2 + 1] * gate + bq[col + 1];
            *reinterpret_cast<float2*>(out + (size_t)row * NDIM + col) = v;
        }
    }
}

// ---------------------------------------------------------------------------
// launch
// ---------------------------------------------------------------------------
extern "C" void kernel_launch(void* const* d_in, const int* in_sizes, int n_in,
                              void* d_out, int out_size) {
    const float* q    = (const float*)d_in[0];   // [64,512,800] f32
    const int*   rdat = (const int*)  d_in[1];   // [64,512]     i32
    const float* Wq   = (const float*)d_in[2];   // [64,800]     f32
    const float* bq   = (const float*)d_in[3];   // [64]         f32
    const float* Wr   = (const float*)d_in[4];   // [1,4]        f32
    const float* br   = (const float*)d_in[5];   // [1]          f32
    float* out = (float*)d_out;                  // [64,512,64]  f32

    convert_B_kernel<<<(NSUB * 2048 + 255) / 256, 256>>>(Wq);

    cudaFuncSetAttribute(ordinal_embed_kernel,
                         cudaFuncAttributeMaxDynamicSharedMemorySize, SMEM_TOTAL);
    ordinal_embed_kernel<<<MDIM / TM, THREADS, SMEM_TOTAL>>>(q, rdat, bq, Wr, br, out);
}